// round 13
// baseline (speedup 1.0000x reference)
#include <cuda_runtime.h>
#include <cstdint>

// Shapes (fixed): x[4,2048,2048] -> M=8192 tokens, D=2048, H=8192
#define TOKS 8192
#define DDIM 2048
#define HDIM 8192
#define EPSV 1e-5f

typedef signed char s8;

// ---- scratch (static device globals; referenced only in device code) ----
__device__ s8    g_xq [(size_t)TOKS * DDIM];
__device__ s8    g_w1q[(size_t)HDIM * DDIM];
__device__ s8    g_w2q[(size_t)DDIM * HDIM];
__device__ s8    g_hq [(size_t)TOKS * HDIM];
__device__ float g_h2 [(size_t)TOKS * HDIM];
__device__ float g_xscale[TOKS];
__device__ float g_hmax[TOKS];            // per-row max of h2 (atomicMax on float bits)
__device__ float g_partial1[4096];
__device__ float g_partial2[4096];
__device__ float g_wmean[2];

// ============================ PTX helpers (portable) ============================
__device__ __forceinline__ uint32_t smem_u32(const void* p) {
    uint32_t a;
    asm("{ .reg .u64 t; cvta.to.shared.u64 t, %1; cvt.u32.u64 %0, t; }" : "=r"(a) : "l"(p));
    return a;
}
__device__ __forceinline__ void cp16(uint32_t dst, const void* src) {
    asm volatile("cp.async.cg.shared.global [%0], [%1], 16;" :: "r"(dst), "l"(src));
}
__device__ __forceinline__ void cp_commit() {
    asm volatile("cp.async.commit_group;" ::: "memory");
}
template <int N> __device__ __forceinline__ void cp_wait() {
    asm volatile("cp.async.wait_group %0;" :: "n"(N) : "memory");
}
__device__ __forceinline__ void bar_grp(int id) {
    asm volatile("bar.sync %0, 128;" :: "r"(id) : "memory");
}
#define LDSM4(r, addr)                                                          \
    asm volatile("ldmatrix.sync.aligned.m8n8.x4.shared.b16 {%0,%1,%2,%3}, [%4];" \
        : "=r"((r)[0]), "=r"((r)[1]), "=r"((r)[2]), "=r"((r)[3]) : "r"(addr))
#define MMA_S8(d, a, b0, b1)                                                    \
    asm volatile("mma.sync.aligned.m16n8k32.row.col.s32.s8.s8.s32 "             \
        "{%0,%1,%2,%3},{%4,%5,%6,%7},{%8,%9},{%0,%1,%2,%3};"                    \
        : "+r"((d)[0]), "+r"((d)[1]), "+r"((d)[2]), "+r"((d)[3])                \
        : "r"((a)[0]), "r"((a)[1]), "r"((a)[2]), "r"((a)[3]), "r"(b0), "r"(b1))

// ============================ aux kernels ============================
__global__ void prep0(const float* __restrict__ x,
                      const float* __restrict__ w1,
                      const float* __restrict__ w2) {
    __shared__ float red[256];
    if (blockIdx.x < TOKS) {
        const int row = blockIdx.x;
        if (threadIdx.x == 1) g_hmax[row] = 0.f;    // zero for gemm0 epilogue atomics
        const float4* x4 = (const float4*)(x + (size_t)row * DDIM);
        const int n4 = DDIM >> 2;
        float mx = 0.f;
        for (int i = threadIdx.x; i < n4; i += 256) {
            float4 v = x4[i];
            mx = fmaxf(mx, fmaxf(fmaxf(fabsf(v.x), fabsf(v.y)),
                                 fmaxf(fabsf(v.z), fabsf(v.w))));
        }
        red[threadIdx.x] = mx;
        __syncthreads();
        for (int o = 128; o > 0; o >>= 1) {
            if (threadIdx.x < o) red[threadIdx.x] = fmaxf(red[threadIdx.x], red[threadIdx.x + o]);
            __syncthreads();
        }
        float scale = 127.f / fmaxf(red[0], EPSV);
        if (threadIdx.x == 0) g_xscale[row] = scale;
        char4* q4 = (char4*)(g_xq + (size_t)row * DDIM);
        for (int i = threadIdx.x; i < n4; i += 256) {
            float4 v = x4[i];
            char4 o;
            o.x = (s8)(int)fminf(127.f, fmaxf(-128.f, rintf(v.x * scale)));
            o.y = (s8)(int)fminf(127.f, fmaxf(-128.f, rintf(v.y * scale)));
            o.z = (s8)(int)fminf(127.f, fmaxf(-128.f, rintf(v.z * scale)));
            o.w = (s8)(int)fminf(127.f, fmaxf(-128.f, rintf(v.w * scale)));
            q4[i] = o;
        }
    } else {
        const int blk = blockIdx.x - TOKS;
#pragma unroll
        for (int which = 0; which < 2; which++) {
            const float* w = which ? w2 : w1;
            float* part = which ? g_partial2 : g_partial1;
            const float4* w4 = (const float4*)(w + (size_t)blk * 4096);
            float s = 0.f;
#pragma unroll
            for (int i = 0; i < 4; i++) {
                float4 v = w4[threadIdx.x + i * 256];
                s += fabsf(v.x) + fabsf(v.y) + fabsf(v.z) + fabsf(v.w);
            }
            red[threadIdx.x] = s;
            __syncthreads();
            for (int o = 128; o > 0; o >>= 1) {
                if (threadIdx.x < o) red[threadIdx.x] += red[threadIdx.x + o];
                __syncthreads();
            }
            if (threadIdx.x == 0) part[blk] = red[0];
            __syncthreads();
        }
    }
}

__global__ void absmean_final_both() {
    __shared__ float red[1024];
#pragma unroll
    for (int which = 0; which < 2; which++) {
        const float* part = which ? g_partial2 : g_partial1;
        float s = part[threadIdx.x] + part[threadIdx.x + 1024] +
                  part[threadIdx.x + 2048] + part[threadIdx.x + 3072];
        red[threadIdx.x] = s;
        __syncthreads();
        for (int o = 512; o > 0; o >>= 1) {
            if (threadIdx.x < o) red[threadIdx.x] += red[threadIdx.x + o];
            __syncthreads();
        }
        if (threadIdx.x == 0) g_wmean[which] = fmaxf(red[0] / 16777216.f, EPSV);
        __syncthreads();
    }
}

__global__ void quantize_w_both(const float* __restrict__ w1, const float* __restrict__ w2) {
    const long n4 = (long)HDIM * DDIM / 4;
    const long stride = (long)gridDim.x * blockDim.x;
#pragma unroll
    for (int idx = 0; idx < 2; idx++) {
        const float* w = idx ? w2 : w1;
        s8* wq = idx ? g_w2q : g_w1q;
        float inv = 1.f / g_wmean[idx];
        const float4* w4 = (const float4*)w;
        char4* q4 = (char4*)wq;
        for (long k = (long)blockIdx.x * blockDim.x + threadIdx.x; k < n4; k += stride) {
            float4 v = w4[k];
            char4 o;
            o.x = (s8)(int)fmaxf(-1.f, fminf(1.f, rintf(v.x * inv)));
            o.y = (s8)(int)fmaxf(-1.f, fminf(1.f, rintf(v.y * inv)));
            o.z = (s8)(int)fmaxf(-1.f, fminf(1.f, rintf(v.z * inv)));
            o.w = (s8)(int)fmaxf(-1.f, fminf(1.f, rintf(v.w * inv)));
            q4[k] = o;
        }
    }
}

// single pass: scale comes from g_hmax (filled by gemm0 epilogue atomics)
__global__ void quantize_rows_h() {
    const int row = blockIdx.x;
    const float scale = 127.f / fmaxf(g_hmax[row], EPSV);
    const float4* x4 = (const float4*)(g_h2 + (size_t)row * HDIM);
    char4* q4 = (char4*)(g_hq + (size_t)row * HDIM);
    const int n4 = HDIM >> 2;
    for (int i = threadIdx.x; i < n4; i += 256) {
        float4 v = x4[i];
        char4 o;
        o.x = (s8)(int)fminf(127.f, fmaxf(-128.f, rintf(v.x * scale)));
        o.y = (s8)(int)fminf(127.f, fmaxf(-128.f, rintf(v.y * scale)));
        o.z = (s8)(int)fminf(127.f, fmaxf(-128.f, rintf(v.z * scale)));
        o.w = (s8)(int)fminf(127.f, fmaxf(-128.f, rintf(v.w * scale)));
        q4[i] = o;
    }
}

// ============================ HYBRID GEMM (2 CTAs/SM) ==============================
// C[m,n] = sum_k A[m,k]*B[n,k]. CTA tile 128x64, 256 threads, 2 CTAs/SM.
// Warps 4-7 (IMMA/tensor): K in [0,Ki), 4-stage cp.async pipeline.
// Warps 0-3 (dp4a/fma):    K in [Ki,K), 64B chunks, single-buffer 2-barrier loop
//   (R10 baseline — proven best among dp4a variants).
// Split 5/8 from MEASURED per-unit-K costs (tensor 1.458, dp4a-effective 2.286):
// both sides then finish together. Partials merged in smem (exact int math).
// gemm0 epilogue also folds the per-row max of h2 into g_hmax (exact atomicMax).
#define STAGES 4
#define A_STG 8192                         // 128 rows x 64B
#define B_STG 4096                         // 64 rows x 64B
#define STAGE_BYTES (A_STG + B_STG)        // 12 KB
#define RING_BYTES (STAGES * STAGE_BYTES)  // 48 KB (reused as merge buffer 128x68 int = 34 KB)
#define DPA_OFF RING_BYTES                 // dp4a A buf: int[16][128] = 8 KB
#define DPB_OFF (RING_BYTES + 8192)        // dp4a B buf: int[16][64]  = 4 KB
#define GEMM_SMEM (RING_BYTES + 12288)     // 60 KB -> 2 CTAs = 120 KB/SM

__global__ __launch_bounds__(256, 2) void gemm_hybrid(int mode, float* __restrict__ outParam) {
    const int Kx = mode ? HDIM : DDIM;
    const int Nx = mode ? DDIM : HDIM;
    const int Ki = mode ? 5120 : 1280;     // tensor K-range (5/8, measured-balanced)
    const s8* __restrict__ A = mode ? g_hq : g_xq;
    const s8* __restrict__ B = mode ? g_w2q : g_w1q;
    float* __restrict__ outp = mode ? outParam : g_h2;
    const float wmean = g_wmean[mode];

    extern __shared__ char smem[];
    const uint32_t sbase = smem_u32(smem);
    int* __restrict__ mg = (int*)smem;     // merge buffer [128][68], reuses ring

    const int tid = threadIdx.x;
    const int wid = tid >> 5;
    const int lane = tid & 31;
    const int m0 = blockIdx.y * 128;
    const int n0 = blockIdx.x * 64;

    int acc[64];
#pragma unroll
    for (int i = 0; i < 64; i++) acc[i] = 0;

    if (wid >= 4) {
        // ========== IMMA path (tensor pipe), warps 4-7, warp tile 32x64 ==========
        const int tg = tid - 128;          // 0..127 within group
        const int warp_m = wid - 4;        // 0..3
        const int q  = lane >> 3;
        const int r8 = lane & 7;

        uint32_t offA[2][2], offB[4][2];
#pragma unroll
        for (int mt = 0; mt < 2; mt++) {
            int row = warp_m * 32 + mt * 16 + (q & 1) * 8 + r8;
            int key = (row >> 1) & 3;
#pragma unroll
            for (int ks = 0; ks < 2; ks++) {
                int c = ks * 2 + (q >> 1);
                offA[mt][ks] = (uint32_t)(row * 64 + ((c ^ key) * 16));
            }
        }
#pragma unroll
        for (int g = 0; g < 4; g++) {
            int row = g * 16 + (q >> 1) * 8 + r8;     // 0..63 (all warps share B)
            int key = (row >> 1) & 3;
#pragma unroll
            for (int ks = 0; ks < 2; ks++) {
                int c = ks * 2 + (q & 1);
                offB[g][ks] = (uint32_t)(A_STG + row * 64 + ((c ^ key) * 16));
            }
        }

        // loaders: A 512 chunks -> 4/thread over 128 threads; B 256 -> 2/thread
        uint32_t soffA[4], soffB[2];
        const s8* gA[4];
        const s8* gB[2];
#pragma unroll
        for (int h = 0; h < 4; h++) {
            int linear = tg + 128 * h;     // 0..511
            int row = linear >> 2;
            int chunk = linear & 3;
            int pc = chunk ^ ((row >> 1) & 3);
            soffA[h] = (uint32_t)(row * 64 + pc * 16);
            gA[h] = A + (size_t)(m0 + row) * Kx + chunk * 16;
        }
#pragma unroll
        for (int h = 0; h < 2; h++) {
            int linear = tg + 128 * h;     // 0..255
            int row = linear >> 2;         // 0..63
            int chunk = linear & 3;
            int pc = chunk ^ ((row >> 1) & 3);
            soffB[h] = (uint32_t)(A_STG + row * 64 + pc * 16);
            gB[h] = B + (size_t)(n0 + row) * Kx + chunk * 16;
        }

        const int T = Ki >> 6;

        auto load_stage = [&](int t) {
            uint32_t st = sbase + (uint32_t)(t % STAGES) * STAGE_BYTES;
            size_t kb = (size_t)t * 64;
#pragma unroll
            for (int h = 0; h < 4; h++) cp16(st + soffA[h], gA[h] + kb);
#pragma unroll
            for (int h = 0; h < 2; h++) cp16(st + soffB[h], gB[h] + kb);
            cp_commit();
        };

#pragma unroll
        for (int t = 0; t < STAGES - 1; t++) load_stage(t);

        for (int t = 0; t < T; t++) {
            cp_wait<STAGES - 2>();
            bar_grp(1);
            if (t + STAGES - 1 < T) load_stage(t + STAGES - 1);

            const uint32_t st = sbase + (uint32_t)(t % STAGES) * STAGE_BYTES;
#pragma unroll
            for (int ks = 0; ks < 2; ks++) {
                uint32_t a[2][4], b[4][4];
#pragma unroll
                for (int mt = 0; mt < 2; mt++) LDSM4(a[mt], st + offA[mt][ks]);
#pragma unroll
                for (int g = 0; g < 4; g++) LDSM4(b[g], st + offB[g][ks]);
#pragma unroll
                for (int mt = 0; mt < 2; mt++)
#pragma unroll
                    for (int nt = 0; nt < 8; nt++) {
                        const int g = nt >> 1, s = (nt & 1) * 2;
                        MMA_S8((acc + (mt * 8 + nt) * 4), a[mt], b[g][s], b[g][s + 1]);
                    }
            }
        }
    } else {
        // ========== dp4a path (fma pipe), warps 0-3, 64B chunks (R10 loop) ==========
        const int t2 = tid;                // 0..127
        const int tr = t2 >> 3;            // 0..15 (row group)
        const int tc = t2 & 7;             // 0..7  (col group)
        int* As = (int*)(smem + DPA_OFF);  // [kk][128], kk = 0..15
        int* Bs = (int*)(smem + DPB_OFF);  // [kk][64]

        int arow[4], aseg[4], brow[2], bseg[2];
        const s8* aP[4];
        const s8* bP[2];
#pragma unroll
        for (int h = 0; h < 4; h++) {
            int linear = t2 + 128 * h;     // 0..511
            arow[h] = linear >> 2;
            aseg[h] = linear & 3;
            aP[h] = A + (size_t)(m0 + arow[h]) * Kx + Ki + aseg[h] * 16;
        }
#pragma unroll
        for (int h = 0; h < 2; h++) {
            int linear = t2 + 128 * h;     // 0..255
            brow[h] = linear >> 2;         // 0..63
            bseg[h] = linear & 3;
            bP[h] = B + (size_t)(n0 + brow[h]) * Kx + Ki + bseg[h] * 16;
        }
        const int Ud = (Kx - Ki) >> 6;     // 64B chunks

        for (int u = 0; u < Ud; u++) {
            int4 av[4], bv[2];
#pragma unroll
            for (int h = 0; h < 4; h++) av[h] = *(const int4*)(aP[h] + (size_t)u * 64);
#pragma unroll
            for (int h = 0; h < 2; h++) bv[h] = *(const int4*)(bP[h] + (size_t)u * 64);
            bar_grp(2);                     // prior chunk's reads done
#pragma unroll
            for (int h = 0; h < 4; h++) {
                As[(aseg[h] * 4 + 0) * 128 + arow[h]] = av[h].x;
                As[(aseg[h] * 4 + 1) * 128 + arow[h]] = av[h].y;
                As[(aseg[h] * 4 + 2) * 128 + arow[h]] = av[h].z;
                As[(aseg[h] * 4 + 3) * 128 + arow[h]] = av[h].w;
            }
#pragma unroll
            for (int h = 0; h < 2; h++) {
                Bs[(bseg[h] * 4 + 0) * 64 + brow[h]] = bv[h].x;
                Bs[(bseg[h] * 4 + 1) * 64 + brow[h]] = bv[h].y;
                Bs[(bseg[h] * 4 + 2) * 64 + brow[h]] = bv[h].z;
                Bs[(bseg[h] * 4 + 3) * 64 + brow[h]] = bv[h].w;
            }
            bar_grp(2);                     // data visible

#pragma unroll
            for (int kk = 0; kk < 16; kk++) {
                int a[8], b[8];
#pragma unroll
                for (int i = 0; i < 8; i++) a[i] = As[kk * 128 + tr + i * 16];
#pragma unroll
                for (int j = 0; j < 8; j++) b[j] = Bs[kk * 64 + tc + j * 8];
#pragma unroll
                for (int i = 0; i < 8; i++)
#pragma unroll
                    for (int j = 0; j < 8; j++)
                        acc[i * 8 + j] = __dp4a(a[i], b[j], acc[i * 8 + j]);
            }
        }
    }

    __syncthreads();   // both groups done; ring is dead

    if (wid < 4) {
        const int t2 = tid;
        const int tr = t2 >> 3;
        const int tc = t2 & 7;
#pragma unroll
        for (int i = 0; i < 8; i++)
#pragma unroll
            for (int j = 0; j < 8; j++)
                mg[(tr + i * 16) * 68 + (tc + j * 8)] = acc[i * 8 + j];
    }

    __syncthreads();

    if (wid >= 4) {
        const int warp_m = wid - 4;
#pragma unroll
        for (int mt = 0; mt < 2; mt++) {
            const int r0l = warp_m * 32 + mt * 16 + (lane >> 2);
            const int mrow = m0 + r0l;
            float fac0, fac8;
            if (mode == 0) {
                fac0 = wmean / g_xscale[mrow];
                fac8 = wmean / g_xscale[mrow + 8];
            } else {
                fac0 = wmean * fmaxf(g_hmax[mrow], EPSV) * (1.f / 127.f);
                fac8 = wmean * fmaxf(g_hmax[mrow + 8], EPSV) * (1.f / 127.f);
            }
            float rmax0 = 0.f, rmax8 = 0.f;
#pragma unroll
            for (int nt = 0; nt < 8; nt++) {
                const int c0l = (lane & 3) * 2 + nt * 8;
                const int col = n0 + c0l;
                const int idx = (mt * 8 + nt) * 4;
                int i0 = acc[idx + 0] + mg[r0l * 68 + c0l];
                int i1 = acc[idx + 1] + mg[r0l * 68 + c0l + 1];
                int i2 = acc[idx + 2] + mg[(r0l + 8) * 68 + c0l];
                int i3 = acc[idx + 3] + mg[(r0l + 8) * 68 + c0l + 1];
                float v0 = (float)i0 * fac0;
                float v1 = (float)i1 * fac0;
                float v2 = (float)i2 * fac8;
                float v3 = (float)i3 * fac8;
                if (mode == 0) {
                    v0 = fmaxf(v0, 0.f); v0 *= v0;
                    v1 = fmaxf(v1, 0.f); v1 *= v1;
                    v2 = fmaxf(v2, 0.f); v2 *= v2;
                    v3 = fmaxf(v3, 0.f); v3 *= v3;
                    rmax0 = fmaxf(rmax0, fmaxf(v0, v1));
                    rmax8 = fmaxf(rmax8, fmaxf(v2, v3));
                }
                *(float2*)(outp + (size_t)mrow * Nx + col)       = make_float2(v0, v1);
                *(float2*)(outp + (size_t)(mrow + 8) * Nx + col) = make_float2(v2, v3);
            }
            if (mode == 0) {
                // h2 >= 0 => float bits order as signed ints: atomicMax is exact
                atomicMax((int*)&g_hmax[mrow],     __float_as_int(rmax0));
                atomicMax((int*)&g_hmax[mrow + 8], __float_as_int(rmax8));
            }
        }
    }
}

// ============================ launch ============================
// gemm_hybrid(mode=0) at launch index 3 (profiler window).
extern "C" void kernel_launch(void* const* d_in, const int* in_sizes, int n_in,
                              void* d_out, int out_size) {
    const float* x  = (const float*)d_in[0];
    const float* w1 = (const float*)d_in[1];
    const float* w2 = (const float*)d_in[2];
    float* out = (float*)d_out;

    cudaFuncSetAttribute(gemm_hybrid, cudaFuncAttributeMaxDynamicSharedMemorySize, GEMM_SMEM);

    prep0<<<TOKS + 4096, 256>>>(x, w1, w2);                // 0
    absmean_final_both<<<1, 1024>>>();                     // 1
    quantize_w_both<<<4096, 256>>>(w1, w2);                // 2

    gemm_hybrid<<<dim3(HDIM / 64, TOKS / 128), 256, GEMM_SMEM>>>(0, nullptr);   // 3 <- ncu

    quantize_rows_h<<<TOKS, 256>>>();                      // 4

    gemm_hybrid<<<dim3(DDIM / 64, TOKS / 128), 256, GEMM_SMEM>>>(1, out);       // 5
}

// round 14
// speedup vs baseline: 1.0645x; 1.0645x over previous
#include <cuda_runtime.h>
#include <cstdint>

// Shapes (fixed): x[4,2048,2048] -> M=8192 tokens, D=2048, H=8192
#define TOKS 8192
#define DDIM 2048
#define HDIM 8192
#define EPSV 1e-5f

typedef signed char s8;

// ---- scratch (static device globals; referenced only in device code) ----
__device__ s8    g_xq [(size_t)TOKS * DDIM];
__device__ s8    g_w1q[(size_t)HDIM * DDIM];
__device__ s8    g_w2q[(size_t)DDIM * HDIM];
__device__ s8    g_hq [(size_t)TOKS * HDIM];
__device__ float g_h2 [(size_t)TOKS * HDIM];
__device__ float g_xscale[TOKS];
__device__ float g_hmax[TOKS];            // per-row max of h2 (atomicMax on float bits)
__device__ float g_partial1[4096];
__device__ float g_partial2[4096];
__device__ float g_wmean[2];

// ============================ PTX helpers (portable) ============================
__device__ __forceinline__ uint32_t smem_u32(const void* p) {
    uint32_t a;
    asm("{ .reg .u64 t; cvta.to.shared.u64 t, %1; cvt.u32.u64 %0, t; }" : "=r"(a) : "l"(p));
    return a;
}
__device__ __forceinline__ void cp16(uint32_t dst, const void* src) {
    asm volatile("cp.async.cg.shared.global [%0], [%1], 16;" :: "r"(dst), "l"(src));
}
__device__ __forceinline__ void cp_commit() {
    asm volatile("cp.async.commit_group;" ::: "memory");
}
template <int N> __device__ __forceinline__ void cp_wait() {
    asm volatile("cp.async.wait_group %0;" :: "n"(N) : "memory");
}
__device__ __forceinline__ void bar_grp(int id) {
    asm volatile("bar.sync %0, 128;" :: "r"(id) : "memory");
}
#define LDSM4(r, addr)                                                          \
    asm volatile("ldmatrix.sync.aligned.m8n8.x4.shared.b16 {%0,%1,%2,%3}, [%4];" \
        : "=r"((r)[0]), "=r"((r)[1]), "=r"((r)[2]), "=r"((r)[3]) : "r"(addr))
#define MMA_S8(d, a, b0, b1)                                                    \
    asm volatile("mma.sync.aligned.m16n8k32.row.col.s32.s8.s8.s32 "             \
        "{%0,%1,%2,%3},{%4,%5,%6,%7},{%8,%9},{%0,%1,%2,%3};"                    \
        : "+r"((d)[0]), "+r"((d)[1]), "+r"((d)[2]), "+r"((d)[3])                \
        : "r"((a)[0]), "r"((a)[1]), "r"((a)[2]), "r"((a)[3]), "r"(b0), "r"(b1))

// ============================ aux kernels ============================
__global__ void prep0(const float* __restrict__ x,
                      const float* __restrict__ w1,
                      const float* __restrict__ w2) {
    __shared__ float red[256];
    if (blockIdx.x < TOKS) {
        const int row = blockIdx.x;
        if (threadIdx.x == 1) g_hmax[row] = 0.f;    // zero for gemm0 epilogue atomics
        const float4* x4 = (const float4*)(x + (size_t)row * DDIM);
        const int n4 = DDIM >> 2;
        float mx = 0.f;
        for (int i = threadIdx.x; i < n4; i += 256) {
            float4 v = x4[i];
            mx = fmaxf(mx, fmaxf(fmaxf(fabsf(v.x), fabsf(v.y)),
                                 fmaxf(fabsf(v.z), fabsf(v.w))));
        }
        red[threadIdx.x] = mx;
        __syncthreads();
        for (int o = 128; o > 0; o >>= 1) {
            if (threadIdx.x < o) red[threadIdx.x] = fmaxf(red[threadIdx.x], red[threadIdx.x + o]);
            __syncthreads();
        }
        float scale = 127.f / fmaxf(red[0], EPSV);
        if (threadIdx.x == 0) g_xscale[row] = scale;
        char4* q4 = (char4*)(g_xq + (size_t)row * DDIM);
        for (int i = threadIdx.x; i < n4; i += 256) {
            float4 v = x4[i];
            char4 o;
            o.x = (s8)(int)fminf(127.f, fmaxf(-128.f, rintf(v.x * scale)));
            o.y = (s8)(int)fminf(127.f, fmaxf(-128.f, rintf(v.y * scale)));
            o.z = (s8)(int)fminf(127.f, fmaxf(-128.f, rintf(v.z * scale)));
            o.w = (s8)(int)fminf(127.f, fmaxf(-128.f, rintf(v.w * scale)));
            q4[i] = o;
        }
    } else {
        const int blk = blockIdx.x - TOKS;
#pragma unroll
        for (int which = 0; which < 2; which++) {
            const float* w = which ? w2 : w1;
            float* part = which ? g_partial2 : g_partial1;
            const float4* w4 = (const float4*)(w + (size_t)blk * 4096);
            float s = 0.f;
#pragma unroll
            for (int i = 0; i < 4; i++) {
                float4 v = w4[threadIdx.x + i * 256];
                s += fabsf(v.x) + fabsf(v.y) + fabsf(v.z) + fabsf(v.w);
            }
            red[threadIdx.x] = s;
            __syncthreads();
            for (int o = 128; o > 0; o >>= 1) {
                if (threadIdx.x < o) red[threadIdx.x] += red[threadIdx.x + o];
                __syncthreads();
            }
            if (threadIdx.x == 0) part[blk] = red[0];
            __syncthreads();
        }
    }
}

__global__ void absmean_final_both() {
    __shared__ float red[1024];
#pragma unroll
    for (int which = 0; which < 2; which++) {
        const float* part = which ? g_partial2 : g_partial1;
        float s = part[threadIdx.x] + part[threadIdx.x + 1024] +
                  part[threadIdx.x + 2048] + part[threadIdx.x + 3072];
        red[threadIdx.x] = s;
        __syncthreads();
        for (int o = 512; o > 0; o >>= 1) {
            if (threadIdx.x < o) red[threadIdx.x] += red[threadIdx.x + o];
            __syncthreads();
        }
        if (threadIdx.x == 0) g_wmean[which] = fmaxf(red[0] / 16777216.f, EPSV);
        __syncthreads();
    }
}

__global__ void quantize_w_both(const float* __restrict__ w1, const float* __restrict__ w2) {
    const long n4 = (long)HDIM * DDIM / 4;
    const long stride = (long)gridDim.x * blockDim.x;
#pragma unroll
    for (int idx = 0; idx < 2; idx++) {
        const float* w = idx ? w2 : w1;
        s8* wq = idx ? g_w2q : g_w1q;
        float inv = 1.f / g_wmean[idx];
        const float4* w4 = (const float4*)w;
        char4* q4 = (char4*)wq;
        for (long k = (long)blockIdx.x * blockDim.x + threadIdx.x; k < n4; k += stride) {
            float4 v = w4[k];
            char4 o;
            o.x = (s8)(int)fmaxf(-1.f, fminf(1.f, rintf(v.x * inv)));
            o.y = (s8)(int)fmaxf(-1.f, fminf(1.f, rintf(v.y * inv)));
            o.z = (s8)(int)fmaxf(-1.f, fminf(1.f, rintf(v.z * inv)));
            o.w = (s8)(int)fmaxf(-1.f, fminf(1.f, rintf(v.w * inv)));
            q4[k] = o;
        }
    }
}

// single pass: scale comes from g_hmax (filled by gemm0 epilogue atomics)
__global__ void quantize_rows_h() {
    const int row = blockIdx.x;
    const float scale = 127.f / fmaxf(g_hmax[row], EPSV);
    const float4* x4 = (const float4*)(g_h2 + (size_t)row * HDIM);
    char4* q4 = (char4*)(g_hq + (size_t)row * HDIM);
    const int n4 = HDIM >> 2;
    for (int i = threadIdx.x; i < n4; i += 256) {
        float4 v = x4[i];
        char4 o;
        o.x = (s8)(int)fminf(127.f, fmaxf(-128.f, rintf(v.x * scale)));
        o.y = (s8)(int)fminf(127.f, fmaxf(-128.f, rintf(v.y * scale)));
        o.z = (s8)(int)fminf(127.f, fmaxf(-128.f, rintf(v.z * scale)));
        o.w = (s8)(int)fminf(127.f, fmaxf(-128.f, rintf(v.w * scale)));
        q4[i] = o;
    }
}

// ============================ HYBRID GEMM (2 CTAs/SM) ==============================
// EXACT R10 GEMM configuration (best: 2524us) + hmax fusion in gemm0 epilogue.
// C[m,n] = sum_k A[m,k]*B[n,k]. CTA tile 128x64, 256 threads, 2 CTAs/SM.
// Warps 4-7 (IMMA/tensor): K in [0,Ki), 4-stage cp.async pipeline.
// Warps 0-3 (dp4a/fma):    K in [Ki,K), 64B chunks, single-buffer 2-barrier loop.
// Split 9/16 = measured lattice optimum (R13 calibration: ct~4142, cd~5472,
// f* = 0.569; 0.5625 beats 0.59375 and 0.625). Partials merged in smem.
#define STAGES 4
#define A_STG 8192                         // 128 rows x 64B
#define B_STG 4096                         // 64 rows x 64B
#define STAGE_BYTES (A_STG + B_STG)        // 12 KB
#define RING_BYTES (STAGES * STAGE_BYTES)  // 48 KB (reused as merge buffer 128x68 int = 34 KB)
#define DPA_OFF RING_BYTES                 // dp4a A buf: int[16][128] = 8 KB
#define DPB_OFF (RING_BYTES + 8192)        // dp4a B buf: int[16][64]  = 4 KB
#define GEMM_SMEM (RING_BYTES + 12288)     // 60 KB -> 2 CTAs = 120 KB/SM

__global__ __launch_bounds__(256, 2) void gemm_hybrid(int mode, float* __restrict__ outParam) {
    const int Kx = mode ? HDIM : DDIM;
    const int Nx = mode ? DDIM : HDIM;
    const int Ki = mode ? 4608 : 1152;     // tensor K-range (9/16)
    const s8* __restrict__ A = mode ? g_hq : g_xq;
    const s8* __restrict__ B = mode ? g_w2q : g_w1q;
    float* __restrict__ outp = mode ? outParam : g_h2;
    const float wmean = g_wmean[mode];

    extern __shared__ char smem[];
    const uint32_t sbase = smem_u32(smem);
    int* __restrict__ mg = (int*)smem;     // merge buffer [128][68], reuses ring

    const int tid = threadIdx.x;
    const int wid = tid >> 5;
    const int lane = tid & 31;
    const int m0 = blockIdx.y * 128;
    const int n0 = blockIdx.x * 64;

    int acc[64];
#pragma unroll
    for (int i = 0; i < 64; i++) acc[i] = 0;

    if (wid >= 4) {
        // ========== IMMA path (tensor pipe), warps 4-7, warp tile 32x64 ==========
        const int tg = tid - 128;          // 0..127 within group
        const int warp_m = wid - 4;        // 0..3
        const int q  = lane >> 3;
        const int r8 = lane & 7;

        uint32_t offA[2][2], offB[4][2];
#pragma unroll
        for (int mt = 0; mt < 2; mt++) {
            int row = warp_m * 32 + mt * 16 + (q & 1) * 8 + r8;
            int key = (row >> 1) & 3;
#pragma unroll
            for (int ks = 0; ks < 2; ks++) {
                int c = ks * 2 + (q >> 1);
                offA[mt][ks] = (uint32_t)(row * 64 + ((c ^ key) * 16));
            }
        }
#pragma unroll
        for (int g = 0; g < 4; g++) {
            int row = g * 16 + (q >> 1) * 8 + r8;     // 0..63 (all warps share B)
            int key = (row >> 1) & 3;
#pragma unroll
            for (int ks = 0; ks < 2; ks++) {
                int c = ks * 2 + (q & 1);
                offB[g][ks] = (uint32_t)(A_STG + row * 64 + ((c ^ key) * 16));
            }
        }

        // loaders: A 512 chunks -> 4/thread over 128 threads; B 256 -> 2/thread
        uint32_t soffA[4], soffB[2];
        const s8* gA[4];
        const s8* gB[2];
#pragma unroll
        for (int h = 0; h < 4; h++) {
            int linear = tg + 128 * h;     // 0..511
            int row = linear >> 2;
            int chunk = linear & 3;
            int pc = chunk ^ ((row >> 1) & 3);
            soffA[h] = (uint32_t)(row * 64 + pc * 16);
            gA[h] = A + (size_t)(m0 + row) * Kx + chunk * 16;
        }
#pragma unroll
        for (int h = 0; h < 2; h++) {
            int linear = tg + 128 * h;     // 0..255
            int row = linear >> 2;         // 0..63
            int chunk = linear & 3;
            int pc = chunk ^ ((row >> 1) & 3);
            soffB[h] = (uint32_t)(A_STG + row * 64 + pc * 16);
            gB[h] = B + (size_t)(n0 + row) * Kx + chunk * 16;
        }

        const int T = Ki >> 6;

        auto load_stage = [&](int t) {
            uint32_t st = sbase + (uint32_t)(t % STAGES) * STAGE_BYTES;
            size_t kb = (size_t)t * 64;
#pragma unroll
            for (int h = 0; h < 4; h++) cp16(st + soffA[h], gA[h] + kb);
#pragma unroll
            for (int h = 0; h < 2; h++) cp16(st + soffB[h], gB[h] + kb);
            cp_commit();
        };

#pragma unroll
        for (int t = 0; t < STAGES - 1; t++) load_stage(t);

        for (int t = 0; t < T; t++) {
            cp_wait<STAGES - 2>();
            bar_grp(1);
            if (t + STAGES - 1 < T) load_stage(t + STAGES - 1);

            const uint32_t st = sbase + (uint32_t)(t % STAGES) * STAGE_BYTES;
#pragma unroll
            for (int ks = 0; ks < 2; ks++) {
                uint32_t a[2][4], b[4][4];
#pragma unroll
                for (int mt = 0; mt < 2; mt++) LDSM4(a[mt], st + offA[mt][ks]);
#pragma unroll
                for (int g = 0; g < 4; g++) LDSM4(b[g], st + offB[g][ks]);
#pragma unroll
                for (int mt = 0; mt < 2; mt++)
#pragma unroll
                    for (int nt = 0; nt < 8; nt++) {
                        const int g = nt >> 1, s = (nt & 1) * 2;
                        MMA_S8((acc + (mt * 8 + nt) * 4), a[mt], b[g][s], b[g][s + 1]);
                    }
            }
        }
    } else {
        // ========== dp4a path (fma pipe), warps 0-3, 64B chunks (R10 loop) ==========
        const int t2 = tid;                // 0..127
        const int tr = t2 >> 3;            // 0..15 (row group)
        const int tc = t2 & 7;             // 0..7  (col group)
        int* As = (int*)(smem + DPA_OFF);  // [kk][128], kk = 0..15
        int* Bs = (int*)(smem + DPB_OFF);  // [kk][64]

        int arow[4], aseg[4], brow[2], bseg[2];
        const s8* aP[4];
        const s8* bP[2];
#pragma unroll
        for (int h = 0; h < 4; h++) {
            int linear = t2 + 128 * h;     // 0..511
            arow[h] = linear >> 2;
            aseg[h] = linear & 3;
            aP[h] = A + (size_t)(m0 + arow[h]) * Kx + Ki + aseg[h] * 16;
        }
#pragma unroll
        for (int h = 0; h < 2; h++) {
            int linear = t2 + 128 * h;     // 0..255
            brow[h] = linear >> 2;         // 0..63
            bseg[h] = linear & 3;
            bP[h] = B + (size_t)(n0 + brow[h]) * Kx + Ki + bseg[h] * 16;
        }
        const int Ud = (Kx - Ki) >> 6;     // 64B chunks

        for (int u = 0; u < Ud; u++) {
            int4 av[4], bv[2];
#pragma unroll
            for (int h = 0; h < 4; h++) av[h] = *(const int4*)(aP[h] + (size_t)u * 64);
#pragma unroll
            for (int h = 0; h < 2; h++) bv[h] = *(const int4*)(bP[h] + (size_t)u * 64);
            bar_grp(2);                     // prior chunk's reads done
#pragma unroll
            for (int h = 0; h < 4; h++) {
                As[(aseg[h] * 4 + 0) * 128 + arow[h]] = av[h].x;
                As[(aseg[h] * 4 + 1) * 128 + arow[h]] = av[h].y;
                As[(aseg[h] * 4 + 2) * 128 + arow[h]] = av[h].z;
                As[(aseg[h] * 4 + 3) * 128 + arow[h]] = av[h].w;
            }
#pragma unroll
            for (int h = 0; h < 2; h++) {
                Bs[(bseg[h] * 4 + 0) * 64 + brow[h]] = bv[h].x;
                Bs[(bseg[h] * 4 + 1) * 64 + brow[h]] = bv[h].y;
                Bs[(bseg[h] * 4 + 2) * 64 + brow[h]] = bv[h].z;
                Bs[(bseg[h] * 4 + 3) * 64 + brow[h]] = bv[h].w;
            }
            bar_grp(2);                     // data visible

#pragma unroll
            for (int kk = 0; kk < 16; kk++) {
                int a[8], b[8];
#pragma unroll
                for (int i = 0; i < 8; i++) a[i] = As[kk * 128 + tr + i * 16];
#pragma unroll
                for (int j = 0; j < 8; j++) b[j] = Bs[kk * 64 + tc + j * 8];
#pragma unroll
                for (int i = 0; i < 8; i++)
#pragma unroll
                    for (int j = 0; j < 8; j++)
                        acc[i * 8 + j] = __dp4a(a[i], b[j], acc[i * 8 + j]);
            }
        }
    }

    __syncthreads();   // both groups done; ring is dead

    if (wid < 4) {
        const int t2 = tid;
        const int tr = t2 >> 3;
        const int tc = t2 & 7;
#pragma unroll
        for (int i = 0; i < 8; i++)
#pragma unroll
            for (int j = 0; j < 8; j++)
                mg[(tr + i * 16) * 68 + (tc + j * 8)] = acc[i * 8 + j];
    }

    __syncthreads();

    if (wid >= 4) {
        const int warp_m = wid - 4;
#pragma unroll
        for (int mt = 0; mt < 2; mt++) {
            const int r0l = warp_m * 32 + mt * 16 + (lane >> 2);
            const int mrow = m0 + r0l;
            float fac0, fac8;
            if (mode == 0) {
                fac0 = wmean / g_xscale[mrow];
                fac8 = wmean / g_xscale[mrow + 8];
            } else {
                fac0 = wmean * fmaxf(g_hmax[mrow], EPSV) * (1.f / 127.f);
                fac8 = wmean * fmaxf(g_hmax[mrow + 8], EPSV) * (1.f / 127.f);
            }
            float rmax0 = 0.f, rmax8 = 0.f;
#pragma unroll
            for (int nt = 0; nt < 8; nt++) {
                const int c0l = (lane & 3) * 2 + nt * 8;
                const int col = n0 + c0l;
                const int idx = (mt * 8 + nt) * 4;
                int i0 = acc[idx + 0] + mg[r0l * 68 + c0l];
                int i1 = acc[idx + 1] + mg[r0l * 68 + c0l + 1];
                int i2 = acc[idx + 2] + mg[(r0l + 8) * 68 + c0l];
                int i3 = acc[idx + 3] + mg[(r0l + 8) * 68 + c0l + 1];
                float v0 = (float)i0 * fac0;
                float v1 = (float)i1 * fac0;
                float v2 = (float)i2 * fac8;
                float v3 = (float)i3 * fac8;
                if (mode == 0) {
                    v0 = fmaxf(v0, 0.f); v0 *= v0;
                    v1 = fmaxf(v1, 0.f); v1 *= v1;
                    v2 = fmaxf(v2, 0.f); v2 *= v2;
                    v3 = fmaxf(v3, 0.f); v3 *= v3;
                    rmax0 = fmaxf(rmax0, fmaxf(v0, v1));
                    rmax8 = fmaxf(rmax8, fmaxf(v2, v3));
                }
                *(float2*)(outp + (size_t)mrow * Nx + col)       = make_float2(v0, v1);
                *(float2*)(outp + (size_t)(mrow + 8) * Nx + col) = make_float2(v2, v3);
            }
            if (mode == 0) {
                // h2 >= 0 => float bits order as signed ints: atomicMax is exact
                atomicMax((int*)&g_hmax[mrow],     __float_as_int(rmax0));
                atomicMax((int*)&g_hmax[mrow + 8], __float_as_int(rmax8));
            }
        }
    }
}

// ============================ launch ============================
// gemm_hybrid(mode=0) at launch index 3 (profiler window).
extern "C" void kernel_launch(void* const* d_in, const int* in_sizes, int n_in,
                              void* d_out, int out_size) {
    const float* x  = (const float*)d_in[0];
    const float* w1 = (const float*)d_in[1];
    const float* w2 = (const float*)d_in[2];
    float* out = (float*)d_out;

    cudaFuncSetAttribute(gemm_hybrid, cudaFuncAttributeMaxDynamicSharedMemorySize, GEMM_SMEM);

    prep0<<<TOKS + 4096, 256>>>(x, w1, w2);                // 0
    absmean_final_both<<<1, 1024>>>();                     // 1
    quantize_w_both<<<4096, 256>>>(w1, w2);                // 2

    gemm_hybrid<<<dim3(HDIM / 64, TOKS / 128), 256, GEMM_SMEM>>>(0, nullptr);   // 3 <- ncu

    quantize_rows_h<<<TOKS, 256>>>();                      // 4

    gemm_hybrid<<<dim3(DDIM / 64, TOKS / 128), 256, GEMM_SMEM>>>(1, out);       // 5
}

// round 15
// speedup vs baseline: 1.0674x; 1.0027x over previous
#include <cuda_runtime.h>
#include <cstdint>

// Shapes (fixed): x[4,2048,2048] -> M=8192 tokens, D=2048, H=8192
#define TOKS 8192
#define DDIM 2048
#define HDIM 8192
#define EPSV 1e-5f

typedef signed char s8;

// ---- scratch (static device globals; referenced only in device code) ----
__device__ s8    g_xq [(size_t)TOKS * DDIM];
__device__ s8    g_w1q[(size_t)HDIM * DDIM];
__device__ s8    g_w2q[(size_t)DDIM * HDIM];
__device__ s8    g_hq [(size_t)TOKS * HDIM];
__device__ float g_h2 [(size_t)TOKS * HDIM];
__device__ float g_xscale[TOKS];
__device__ float g_hmax[TOKS];            // per-row max of h2 (atomicMax on float bits)
__device__ float g_partial1[4096];
__device__ float g_partial2[4096];
__device__ float g_wmean[2];

// ============================ PTX helpers (portable) ============================
__device__ __forceinline__ uint32_t smem_u32(const void* p) {
    uint32_t a;
    asm("{ .reg .u64 t; cvta.to.shared.u64 t, %1; cvt.u32.u64 %0, t; }" : "=r"(a) : "l"(p));
    return a;
}
__device__ __forceinline__ void cp16(uint32_t dst, const void* src) {
    asm volatile("cp.async.cg.shared.global [%0], [%1], 16;" :: "r"(dst), "l"(src));
}
__device__ __forceinline__ void cp_commit() {
    asm volatile("cp.async.commit_group;" ::: "memory");
}
template <int N> __device__ __forceinline__ void cp_wait() {
    asm volatile("cp.async.wait_group %0;" :: "n"(N) : "memory");
}
__device__ __forceinline__ void bar_grp(int id) {
    asm volatile("bar.sync %0, 128;" :: "r"(id) : "memory");
}
#define LDSM4(r, addr)                                                          \
    asm volatile("ldmatrix.sync.aligned.m8n8.x4.shared.b16 {%0,%1,%2,%3}, [%4];" \
        : "=r"((r)[0]), "=r"((r)[1]), "=r"((r)[2]), "=r"((r)[3]) : "r"(addr))
#define MMA_S8(d, a, b0, b1)                                                    \
    asm volatile("mma.sync.aligned.m16n8k32.row.col.s32.s8.s8.s32 "             \
        "{%0,%1,%2,%3},{%4,%5,%6,%7},{%8,%9},{%0,%1,%2,%3};"                    \
        : "+r"((d)[0]), "+r"((d)[1]), "+r"((d)[2]), "+r"((d)[3])                \
        : "r"((a)[0]), "r"((a)[1]), "r"((a)[2]), "r"((a)[3]), "r"(b0), "r"(b1))

// ============================ aux kernels ============================
__global__ void prep0(const float* __restrict__ x,
                      const float* __restrict__ w1,
                      const float* __restrict__ w2) {
    __shared__ float red[256];
    if (blockIdx.x < TOKS) {
        const int row = blockIdx.x;
        if (threadIdx.x == 1) g_hmax[row] = 0.f;    // zero for gemm0 epilogue atomics
        const float4* x4 = (const float4*)(x + (size_t)row * DDIM);
        const int n4 = DDIM >> 2;
        float mx = 0.f;
        for (int i = threadIdx.x; i < n4; i += 256) {
            float4 v = x4[i];
            mx = fmaxf(mx, fmaxf(fmaxf(fabsf(v.x), fabsf(v.y)),
                                 fmaxf(fabsf(v.z), fabsf(v.w))));
        }
        red[threadIdx.x] = mx;
        __syncthreads();
        for (int o = 128; o > 0; o >>= 1) {
            if (threadIdx.x < o) red[threadIdx.x] = fmaxf(red[threadIdx.x], red[threadIdx.x + o]);
            __syncthreads();
        }
        float scale = 127.f / fmaxf(red[0], EPSV);
        if (threadIdx.x == 0) g_xscale[row] = scale;
        char4* q4 = (char4*)(g_xq + (size_t)row * DDIM);
        for (int i = threadIdx.x; i < n4; i += 256) {
            float4 v = x4[i];
            char4 o;
            o.x = (s8)(int)fminf(127.f, fmaxf(-128.f, rintf(v.x * scale)));
            o.y = (s8)(int)fminf(127.f, fmaxf(-128.f, rintf(v.y * scale)));
            o.z = (s8)(int)fminf(127.f, fmaxf(-128.f, rintf(v.z * scale)));
            o.w = (s8)(int)fminf(127.f, fmaxf(-128.f, rintf(v.w * scale)));
            q4[i] = o;
        }
    } else {
        const int blk = blockIdx.x - TOKS;
#pragma unroll
        for (int which = 0; which < 2; which++) {
            const float* w = which ? w2 : w1;
            float* part = which ? g_partial2 : g_partial1;
            const float4* w4 = (const float4*)(w + (size_t)blk * 4096);
            float s = 0.f;
#pragma unroll
            for (int i = 0; i < 4; i++) {
                float4 v = w4[threadIdx.x + i * 256];
                s += fabsf(v.x) + fabsf(v.y) + fabsf(v.z) + fabsf(v.w);
            }
            red[threadIdx.x] = s;
            __syncthreads();
            for (int o = 128; o > 0; o >>= 1) {
                if (threadIdx.x < o) red[threadIdx.x] += red[threadIdx.x + o];
                __syncthreads();
            }
            if (threadIdx.x == 0) part[blk] = red[0];
            __syncthreads();
        }
    }
}

__global__ void absmean_final_both() {
    __shared__ float red[1024];
#pragma unroll
    for (int which = 0; which < 2; which++) {
        const float* part = which ? g_partial2 : g_partial1;
        float s = part[threadIdx.x] + part[threadIdx.x + 1024] +
                  part[threadIdx.x + 2048] + part[threadIdx.x + 3072];
        red[threadIdx.x] = s;
        __syncthreads();
        for (int o = 512; o > 0; o >>= 1) {
            if (threadIdx.x < o) red[threadIdx.x] += red[threadIdx.x + o];
            __syncthreads();
        }
        if (threadIdx.x == 0) g_wmean[which] = fmaxf(red[0] / 16777216.f, EPSV);
        __syncthreads();
    }
}

__global__ void quantize_w_both(const float* __restrict__ w1, const float* __restrict__ w2) {
    const long n4 = (long)HDIM * DDIM / 4;
    const long stride = (long)gridDim.x * blockDim.x;
#pragma unroll
    for (int idx = 0; idx < 2; idx++) {
        const float* w = idx ? w2 : w1;
        s8* wq = idx ? g_w2q : g_w1q;
        float inv = 1.f / g_wmean[idx];
        const float4* w4 = (const float4*)w;
        char4* q4 = (char4*)wq;
        for (long k = (long)blockIdx.x * blockDim.x + threadIdx.x; k < n4; k += stride) {
            float4 v = w4[k];
            char4 o;
            o.x = (s8)(int)fmaxf(-1.f, fminf(1.f, rintf(v.x * inv)));
            o.y = (s8)(int)fmaxf(-1.f, fminf(1.f, rintf(v.y * inv)));
            o.z = (s8)(int)fmaxf(-1.f, fminf(1.f, rintf(v.z * inv)));
            o.w = (s8)(int)fmaxf(-1.f, fminf(1.f, rintf(v.w * inv)));
            q4[k] = o;
        }
    }
}

// single pass: scale comes from g_hmax (filled by gemm0 epilogue atomics)
__global__ void quantize_rows_h() {
    const int row = blockIdx.x;
    const float scale = 127.f / fmaxf(g_hmax[row], EPSV);
    const float4* x4 = (const float4*)(g_h2 + (size_t)row * HDIM);
    char4* q4 = (char4*)(g_hq + (size_t)row * HDIM);
    const int n4 = HDIM >> 2;
    for (int i = threadIdx.x; i < n4; i += 256) {
        float4 v = x4[i];
        char4 o;
        o.x = (s8)(int)fminf(127.f, fmaxf(-128.f, rintf(v.x * scale)));
        o.y = (s8)(int)fminf(127.f, fmaxf(-128.f, rintf(v.y * scale)));
        o.z = (s8)(int)fminf(127.f, fmaxf(-128.f, rintf(v.z * scale)));
        o.w = (s8)(int)fminf(127.f, fmaxf(-128.f, rintf(v.w * scale)));
        q4[i] = o;
    }
}

// ============================ HYBRID GEMM (2 CTAs/SM) ==============================
// R14 config + dp4a micro-tile reshaped for vectorized LDS:
// each dp4a thread owns 8 CONSECUTIVE rows (r0) x 8 CONSECUTIVE cols (c0), so
// per kk-step A and B slices load with 2+2 ld.shared.v4 (4 LDS instr vs 16),
// conflict-free (A: 4 distinct 16B addrs/warp, B: 8 distinct -> 1 phase each).
// Warps 4-7 (IMMA/tensor): K in [0,Ki), 4-stage cp.async pipeline.
// Warps 0-3 (dp4a/fma):    K in [Ki,K), 64B chunks, single-buffer 2-barrier loop.
// Split 9/16 (lattice optimum from R13 calibration). Partials merged in smem.
#define STAGES 4
#define A_STG 8192                         // 128 rows x 64B
#define B_STG 4096                         // 64 rows x 64B
#define STAGE_BYTES (A_STG + B_STG)        // 12 KB
#define RING_BYTES (STAGES * STAGE_BYTES)  // 48 KB (reused as merge buffer 128x68 int = 34 KB)
#define DPA_OFF RING_BYTES                 // dp4a A buf: int[16][128] = 8 KB
#define DPB_OFF (RING_BYTES + 8192)        // dp4a B buf: int[16][64]  = 4 KB
#define GEMM_SMEM (RING_BYTES + 12288)     // 60 KB -> 2 CTAs = 120 KB/SM

__global__ __launch_bounds__(256, 2) void gemm_hybrid(int mode, float* __restrict__ outParam) {
    const int Kx = mode ? HDIM : DDIM;
    const int Nx = mode ? DDIM : HDIM;
    const int Ki = mode ? 4608 : 1152;     // tensor K-range (9/16)
    const s8* __restrict__ A = mode ? g_hq : g_xq;
    const s8* __restrict__ B = mode ? g_w2q : g_w1q;
    float* __restrict__ outp = mode ? outParam : g_h2;
    const float wmean = g_wmean[mode];

    extern __shared__ char smem[];
    const uint32_t sbase = smem_u32(smem);
    int* __restrict__ mg = (int*)smem;     // merge buffer [128][68], reuses ring

    const int tid = threadIdx.x;
    const int wid = tid >> 5;
    const int lane = tid & 31;
    const int m0 = blockIdx.y * 128;
    const int n0 = blockIdx.x * 64;

    int acc[64];
#pragma unroll
    for (int i = 0; i < 64; i++) acc[i] = 0;

    if (wid >= 4) {
        // ========== IMMA path (tensor pipe), warps 4-7, warp tile 32x64 ==========
        const int tg = tid - 128;          // 0..127 within group
        const int warp_m = wid - 4;        // 0..3
        const int q  = lane >> 3;
        const int r8 = lane & 7;

        uint32_t offA[2][2], offB[4][2];
#pragma unroll
        for (int mt = 0; mt < 2; mt++) {
            int row = warp_m * 32 + mt * 16 + (q & 1) * 8 + r8;
            int key = (row >> 1) & 3;
#pragma unroll
            for (int ks = 0; ks < 2; ks++) {
                int c = ks * 2 + (q >> 1);
                offA[mt][ks] = (uint32_t)(row * 64 + ((c ^ key) * 16));
            }
        }
#pragma unroll
        for (int g = 0; g < 4; g++) {
            int row = g * 16 + (q >> 1) * 8 + r8;     // 0..63 (all warps share B)
            int key = (row >> 1) & 3;
#pragma unroll
            for (int ks = 0; ks < 2; ks++) {
                int c = ks * 2 + (q & 1);
                offB[g][ks] = (uint32_t)(A_STG + row * 64 + ((c ^ key) * 16));
            }
        }

        // loaders: A 512 chunks -> 4/thread over 128 threads; B 256 -> 2/thread
        uint32_t soffA[4], soffB[2];
        const s8* gA[4];
        const s8* gB[2];
#pragma unroll
        for (int h = 0; h < 4; h++) {
            int linear = tg + 128 * h;     // 0..511
            int row = linear >> 2;
            int chunk = linear & 3;
            int pc = chunk ^ ((row >> 1) & 3);
            soffA[h] = (uint32_t)(row * 64 + pc * 16);
            gA[h] = A + (size_t)(m0 + row) * Kx + chunk * 16;
        }
#pragma unroll
        for (int h = 0; h < 2; h++) {
            int linear = tg + 128 * h;     // 0..255
            int row = linear >> 2;         // 0..63
            int chunk = linear & 3;
            int pc = chunk ^ ((row >> 1) & 3);
            soffB[h] = (uint32_t)(A_STG + row * 64 + pc * 16);
            gB[h] = B + (size_t)(n0 + row) * Kx + chunk * 16;
        }

        const int T = Ki >> 6;

        auto load_stage = [&](int t) {
            uint32_t st = sbase + (uint32_t)(t % STAGES) * STAGE_BYTES;
            size_t kb = (size_t)t * 64;
#pragma unroll
            for (int h = 0; h < 4; h++) cp16(st + soffA[h], gA[h] + kb);
#pragma unroll
            for (int h = 0; h < 2; h++) cp16(st + soffB[h], gB[h] + kb);
            cp_commit();
        };

#pragma unroll
        for (int t = 0; t < STAGES - 1; t++) load_stage(t);

        for (int t = 0; t < T; t++) {
            cp_wait<STAGES - 2>();
            bar_grp(1);
            if (t + STAGES - 1 < T) load_stage(t + STAGES - 1);

            const uint32_t st = sbase + (uint32_t)(t % STAGES) * STAGE_BYTES;
#pragma unroll
            for (int ks = 0; ks < 2; ks++) {
                uint32_t a[2][4], b[4][4];
#pragma unroll
                for (int mt = 0; mt < 2; mt++) LDSM4(a[mt], st + offA[mt][ks]);
#pragma unroll
                for (int g = 0; g < 4; g++) LDSM4(b[g], st + offB[g][ks]);
#pragma unroll
                for (int mt = 0; mt < 2; mt++)
#pragma unroll
                    for (int nt = 0; nt < 8; nt++) {
                        const int g = nt >> 1, s = (nt & 1) * 2;
                        MMA_S8((acc + (mt * 8 + nt) * 4), a[mt], b[g][s], b[g][s + 1]);
                    }
            }
        }
    } else {
        // ========== dp4a path (fma pipe), warps 0-3, 64B chunks, v4 LDS ==========
        const int t2 = tid;                // 0..127
        const int r0 = (t2 >> 3) * 8;      // 8 consecutive rows
        const int c0 = (t2 & 7) * 8;       // 8 consecutive cols
        int* As = (int*)(smem + DPA_OFF);  // [kk][128], kk = 0..15
        int* Bs = (int*)(smem + DPB_OFF);  // [kk][64]

        int arow[4], aseg[4], brow[2], bseg[2];
        const s8* aP[4];
        const s8* bP[2];
#pragma unroll
        for (int h = 0; h < 4; h++) {
            int linear = t2 + 128 * h;     // 0..511
            arow[h] = linear >> 2;
            aseg[h] = linear & 3;
            aP[h] = A + (size_t)(m0 + arow[h]) * Kx + Ki + aseg[h] * 16;
        }
#pragma unroll
        for (int h = 0; h < 2; h++) {
            int linear = t2 + 128 * h;     // 0..255
            brow[h] = linear >> 2;         // 0..63
            bseg[h] = linear & 3;
            bP[h] = B + (size_t)(n0 + brow[h]) * Kx + Ki + bseg[h] * 16;
        }
        const int Ud = (Kx - Ki) >> 6;     // 64B chunks

        for (int u = 0; u < Ud; u++) {
            int4 av[4], bv[2];
#pragma unroll
            for (int h = 0; h < 4; h++) av[h] = *(const int4*)(aP[h] + (size_t)u * 64);
#pragma unroll
            for (int h = 0; h < 2; h++) bv[h] = *(const int4*)(bP[h] + (size_t)u * 64);
            bar_grp(2);                     // prior chunk's reads done
#pragma unroll
            for (int h = 0; h < 4; h++) {
                As[(aseg[h] * 4 + 0) * 128 + arow[h]] = av[h].x;
                As[(aseg[h] * 4 + 1) * 128 + arow[h]] = av[h].y;
                As[(aseg[h] * 4 + 2) * 128 + arow[h]] = av[h].z;
                As[(aseg[h] * 4 + 3) * 128 + arow[h]] = av[h].w;
            }
#pragma unroll
            for (int h = 0; h < 2; h++) {
                Bs[(bseg[h] * 4 + 0) * 64 + brow[h]] = bv[h].x;
                Bs[(bseg[h] * 4 + 1) * 64 + brow[h]] = bv[h].y;
                Bs[(bseg[h] * 4 + 2) * 64 + brow[h]] = bv[h].z;
                Bs[(bseg[h] * 4 + 3) * 64 + brow[h]] = bv[h].w;
            }
            bar_grp(2);                     // data visible

#pragma unroll
            for (int kk = 0; kk < 16; kk++) {
                int4 a0 = *(const int4*)&As[kk * 128 + r0];
                int4 a1 = *(const int4*)&As[kk * 128 + r0 + 4];
                int4 b0 = *(const int4*)&Bs[kk * 64 + c0];
                int4 b1 = *(const int4*)&Bs[kk * 64 + c0 + 4];
                int a[8] = {a0.x, a0.y, a0.z, a0.w, a1.x, a1.y, a1.z, a1.w};
                int b[8] = {b0.x, b0.y, b0.z, b0.w, b1.x, b1.y, b1.z, b1.w};
#pragma unroll
                for (int i = 0; i < 8; i++)
#pragma unroll
                    for (int j = 0; j < 8; j++)
                        acc[i * 8 + j] = __dp4a(a[i], b[j], acc[i * 8 + j]);
            }
        }
    }

    __syncthreads();   // both groups done; ring is dead

    if (wid < 4) {
        const int t2 = tid;
        const int r0 = (t2 >> 3) * 8;
        const int c0 = (t2 & 7) * 8;
#pragma unroll
        for (int i = 0; i < 8; i++)
#pragma unroll
            for (int j = 0; j < 8; j++)
                mg[(r0 + i) * 68 + (c0 + j)] = acc[i * 8 + j];
    }

    __syncthreads();

    if (wid >= 4) {
        const int warp_m = wid - 4;
#pragma unroll
        for (int mt = 0; mt < 2; mt++) {
            const int r0l = warp_m * 32 + mt * 16 + (lane >> 2);
            const int mrow = m0 + r0l;
            float fac0, fac8;
            if (mode == 0) {
                fac0 = wmean / g_xscale[mrow];
                fac8 = wmean / g_xscale[mrow + 8];
            } else {
                fac0 = wmean * fmaxf(g_hmax[mrow], EPSV) * (1.f / 127.f);
                fac8 = wmean * fmaxf(g_hmax[mrow + 8], EPSV) * (1.f / 127.f);
            }
            float rmax0 = 0.f, rmax8 = 0.f;
#pragma unroll
            for (int nt = 0; nt < 8; nt++) {
                const int c0l = (lane & 3) * 2 + nt * 8;
                const int col = n0 + c0l;
                const int idx = (mt * 8 + nt) * 4;
                int i0 = acc[idx + 0] + mg[r0l * 68 + c0l];
                int i1 = acc[idx + 1] + mg[r0l * 68 + c0l + 1];
                int i2 = acc[idx + 2] + mg[(r0l + 8) * 68 + c0l];
                int i3 = acc[idx + 3] + mg[(r0l + 8) * 68 + c0l + 1];
                float v0 = (float)i0 * fac0;
                float v1 = (float)i1 * fac0;
                float v2 = (float)i2 * fac8;
                float v3 = (float)i3 * fac8;
                if (mode == 0) {
                    v0 = fmaxf(v0, 0.f); v0 *= v0;
                    v1 = fmaxf(v1, 0.f); v1 *= v1;
                    v2 = fmaxf(v2, 0.f); v2 *= v2;
                    v3 = fmaxf(v3, 0.f); v3 *= v3;
                    rmax0 = fmaxf(rmax0, fmaxf(v0, v1));
                    rmax8 = fmaxf(rmax8, fmaxf(v2, v3));
                }
                *(float2*)(outp + (size_t)mrow * Nx + col)       = make_float2(v0, v1);
                *(float2*)(outp + (size_t)(mrow + 8) * Nx + col) = make_float2(v2, v3);
            }
            if (mode == 0) {
                // h2 >= 0 => float bits order as signed ints: atomicMax is exact
                atomicMax((int*)&g_hmax[mrow],     __float_as_int(rmax0));
                atomicMax((int*)&g_hmax[mrow + 8], __float_as_int(rmax8));
            }
        }
    }
}

// ============================ launch ============================
// gemm_hybrid(mode=0) at launch index 3 (profiler window).
extern "C" void kernel_launch(void* const* d_in, const int* in_sizes, int n_in,
                              void* d_out, int out_size) {
    const float* x  = (const float*)d_in[0];
    const float* w1 = (const float*)d_in[1];
    const float* w2 = (const float*)d_in[2];
    float* out = (float*)d_out;

    cudaFuncSetAttribute(gemm_hybrid, cudaFuncAttributeMaxDynamicSharedMemorySize, GEMM_SMEM);

    prep0<<<TOKS + 4096, 256>>>(x, w1, w2);                // 0
    absmean_final_both<<<1, 1024>>>();                     // 1
    quantize_w_both<<<4096, 256>>>(w1, w2);                // 2

    gemm_hybrid<<<dim3(HDIM / 64, TOKS / 128), 256, GEMM_SMEM>>>(0, nullptr);   // 3 <- ncu

    quantize_rows_h<<<TOKS, 256>>>();                      // 4

    gemm_hybrid<<<dim3(DDIM / 64, TOKS / 128), 256, GEMM_SMEM>>>(1, out);       // 5
}